// round 3
// baseline (speedup 1.0000x reference)
#include <cuda_runtime.h>

#define HID 64
typedef unsigned long long u64;

__device__ __forceinline__ u64 pk2(float lo, float hi) {
    u64 r; asm("mov.b64 %0, {%1,%2};" : "=l"(r) : "f"(lo), "f"(hi)); return r;
}
__device__ __forceinline__ void upk2(u64 v, float& lo, float& hi) {
    asm("mov.b64 {%0,%1}, %2;" : "=f"(lo), "=f"(hi) : "l"(v));
}
__device__ __forceinline__ u64 ffma2(u64 a, u64 b, u64 c) {
    u64 d; asm("fma.rn.f32x2 %0, %1, %2, %3;" : "=l"(d) : "l"(a), "l"(b), "l"(c)); return d;
}
__device__ __forceinline__ u64 fmul2(u64 a, u64 b) {
    u64 d; asm("mul.rn.f32x2 %0, %1, %2;" : "=l"(d) : "l"(a), "l"(b)); return d;
}

__global__ void zero_kernel(float* __restrict__ out, int n) {
    int i = blockIdx.x * blockDim.x + threadIdx.x;
    if (i < n) out[i] = 0.0f;
}

// Per-h weight block in smem: 16 u64 (128B), all values duplicated (w,w):
//   DIN=3: [w1_0..w1_2, b1, w2_0..w2_8, pad, pad, pad]
//   DIN=6: [w1_0..w1_5, b1, w2_0..w2_8]            (exactly 16)
// Loaded with 8x LDS.128 per h — broadcast, conflict-free.
template<int DIN, int EPT>
__device__ __forceinline__ void run_family(
    const float* __restrict__ x,
    const int*   __restrict__ edges,
    const float* __restrict__ attr,
    const float* __restrict__ W1, const float* __restrict__ b1,
    const float* __restrict__ W2, const float* __restrict__ b2,
    float* __restrict__ out, int E, int blk, int nblk, u64* smem)
{
    u64* sWB = smem;              // [16 * HID] per-h blocks
    u64* sB2 = sWB + 16 * HID;    // [9]

    for (int idx = threadIdx.x; idx < 16 * HID; idx += blockDim.x) {
        int h = idx >> 4, s = idx & 15;
        float w = 0.0f;
        if (s < DIN)                w = W1[s * HID + h];
        else if (s == DIN)          w = b1[h];
        else if (s <= DIN + 9)      w = W2[h * 9 + (s - DIN - 1)];
        sWB[idx] = pk2(w, w);
    }
    if (threadIdx.x < 9) { float w = b2[threadIdx.x]; sB2[threadIdx.x] = pk2(w, w); }
    __syncthreads();

    const int famTid     = blk * (int)blockDim.x + (int)threadIdx.x;
    const int famThreads = nblk * (int)blockDim.x;
    constexpr int NP = EPT / 2;

    u64  dp[NP][DIN];     // MLP inputs packed across edge pair
    u64  accp[NP][9];     // mobility accumulators packed across edge pair
    int  tgt[EPT];
    bool valid[EPT];

    #pragma unroll
    for (int p = 0; p < NP; p++) {
        float dv[2][DIN];
        #pragma unroll
        for (int s = 0; s < 2; s++) {
            int k = 2 * p + s;
            int e = famTid + k * famThreads;
            valid[k] = (e < E);
            int ee = valid[k] ? e : 0;
            int i;
            if (DIN == 3) {
                int j = edges[ee];
                i = edges[E + ee];
                dv[s][0] = x[3*j+0] - x[3*i+0];
                dv[s][1] = x[3*j+1] - x[3*i+1];
                dv[s][2] = x[3*j+2] - x[3*i+2];
            } else {
                int j  = edges[ee];
                int kk = edges[E + ee];
                i = edges[2*E + ee];
                float xk0 = x[3*kk+0], xk1 = x[3*kk+1], xk2 = x[3*kk+2];
                dv[s][0] = xk0 - x[3*j+0];
                dv[s][1] = xk1 - x[3*j+1];
                dv[s][2] = xk2 - x[3*j+2];
                dv[s][3] = x[3*i+0] - xk0;
                dv[s][4] = x[3*i+1] - xk1;
                dv[s][5] = x[3*i+2] - xk2;
            }
            tgt[k] = i;
        }
        #pragma unroll
        for (int i = 0; i < DIN; i++) dp[p][i] = pk2(dv[0][i], dv[1][i]);
        #pragma unroll
        for (int m = 0; m < 9; m++) accp[p][m] = sB2[m];
    }

    // Mainloop: per h, 8x LDS.128 (dup-pair weights), packed FMAs over NP pairs.
    #pragma unroll 2
    for (int h = 0; h < HID; h++) {
        const ulonglong2* wrow = (const ulonglong2*)(sWB + h * 16);
        ulonglong2 q[8];
        #pragma unroll
        for (int i = 0; i < 8; i++) q[i] = wrow[i];

        u64 w1p[DIN], bh, w2p[9];
        #pragma unroll
        for (int i = 0; i < DIN; i++) w1p[i] = (i & 1) ? q[i >> 1].y : q[i >> 1].x;
        bh = (DIN & 1) ? q[DIN >> 1].y : q[DIN >> 1].x;
        #pragma unroll
        for (int m = 0; m < 9; m++) {
            int j = DIN + 1 + m;
            w2p[m] = (j & 1) ? q[j >> 1].y : q[j >> 1].x;
        }

        #pragma unroll
        for (int p = 0; p < NP; p++) {
            u64 hv = bh;
            #pragma unroll
            for (int i = 0; i < DIN; i++) hv = ffma2(dp[p][i], w1p[i], hv);
            float lo, hi; upk2(hv, lo, hi);
            lo = fmaxf(lo, 0.0f); hi = fmaxf(hi, 0.0f);
            hv = pk2(lo, hi);
            #pragma unroll
            for (int m = 0; m < 9; m++) accp[p][m] = ffma2(hv, w2p[m], accp[p][m]);
        }
    }

    // Epilogue: load attrs NOW (not live through mainloop), packed matvec, scatter.
    #pragma unroll
    for (int p = 0; p < NP; p++) {
        int e0 = famTid + (2*p+0) * famThreads;
        int e1 = famTid + (2*p+1) * famThreads;
        int ee0 = valid[2*p+0] ? e0 : 0;
        int ee1 = valid[2*p+1] ? e1 : 0;
        u64 atp[3];
        #pragma unroll
        for (int j = 0; j < 3; j++) atp[j] = pk2(attr[3*ee0+j], attr[3*ee1+j]);
        #pragma unroll
        for (int i = 0; i < 3; i++) {
            u64 t = fmul2(accp[p][3*i+2], atp[2]);
            t = ffma2(accp[p][3*i+1], atp[1], t);
            t = ffma2(accp[p][3*i+0], atp[0], t);
            float ylo, yhi; upk2(t, ylo, yhi);
            if (valid[2*p+0]) atomicAdd(&out[3*tgt[2*p+0] + i], ylo);
            if (valid[2*p+1]) atomicAdd(&out[3*tgt[2*p+1] + i], yhi);
        }
    }
}

__global__ __launch_bounds__(128)
void fused_hignn_kernel(
    const float* __restrict__ x,
    const int* __restrict__ e2, const float* __restrict__ a2,
    const float* __restrict__ W1_2b, const float* __restrict__ b1_2b,
    const float* __restrict__ W2_2b, const float* __restrict__ b2_2b,
    const int* __restrict__ e3, const float* __restrict__ a3,
    const float* __restrict__ W1_3b, const float* __restrict__ b1_3b,
    const float* __restrict__ W2_3b, const float* __restrict__ b2_3b,
    const int* __restrict__ es, const float* __restrict__ as,
    const float* __restrict__ W1_s, const float* __restrict__ b1_s,
    const float* __restrict__ W2_s, const float* __restrict__ b2_s,
    float* __restrict__ out,
    int E2, int E3, int ES, int B2, int B3, int BS)
{
    __shared__ __align__(16) u64 smem[16 * HID + 9];
    int b = blockIdx.x;
    if (b < B2) {
        run_family<3, 6>(x, e2, a2, W1_2b, b1_2b, W2_2b, b2_2b, out, E2, b, B2, smem);
    } else if (b < B2 + B3) {
        run_family<6, 6>(x, e3, a3, W1_3b, b1_3b, W2_3b, b2_3b, out, E3, b - B2, B3, smem);
    } else {
        run_family<3, 6>(x, es, as, W1_s, b1_s, W2_s, b2_s, out, ES, b - B2 - B3, BS, smem);
    }
}

extern "C" void kernel_launch(void* const* d_in, const int* in_sizes, int n_in,
                              void* d_out, int out_size)
{
    const float* x   = (const float*)d_in[0];
    const int*   e2  = (const int*)  d_in[1];
    const int*   e3  = (const int*)  d_in[2];
    const int*   es  = (const int*)  d_in[3];
    const float* a2  = (const float*)d_in[5];
    const float* a3  = (const float*)d_in[6];
    const float* as  = (const float*)d_in[7];
    const float* W1_2b = (const float*)d_in[9];
    const float* b1_2b = (const float*)d_in[10];
    const float* W2_2b = (const float*)d_in[11];
    const float* b2_2b = (const float*)d_in[12];
    const float* W1_3b = (const float*)d_in[13];
    const float* b1_3b = (const float*)d_in[14];
    const float* W2_3b = (const float*)d_in[15];
    const float* b2_3b = (const float*)d_in[16];
    const float* W1_s  = (const float*)d_in[17];
    const float* b1_s  = (const float*)d_in[18];
    const float* W2_s  = (const float*)d_in[19];
    const float* b2_s  = (const float*)d_in[20];

    const int E2 = in_sizes[1] / 2;
    const int E3 = in_sizes[2] / 3;
    const int ES = in_sizes[3] / 2;

    float* out = (float*)d_out;

    zero_kernel<<<(out_size + 255) / 256, 256>>>(out, out_size);

    constexpr int EPT = 6;
    constexpr int BLK = 128;
    const int B2 = (E2 + EPT * BLK - 1) / (EPT * BLK);
    const int B3 = (E3 + EPT * BLK - 1) / (EPT * BLK);
    const int BS = (ES + EPT * BLK - 1) / (EPT * BLK);

    fused_hignn_kernel<<<B2 + B3 + BS, BLK>>>(
        x,
        e2, a2, W1_2b, b1_2b, W2_2b, b2_2b,
        e3, a3, W1_3b, b1_3b, W2_3b, b2_3b,
        es, as, W1_s, b1_s, W2_s, b2_s,
        out, E2, E3, ES, B2, B3, BS);
}

// round 4
// speedup vs baseline: 1.0911x; 1.0911x over previous
#include <cuda_runtime.h>

#define HID 64
typedef unsigned long long u64;

__device__ __forceinline__ u64 pk2(float lo, float hi) {
    u64 r; asm("mov.b64 %0, {%1,%2};" : "=l"(r) : "f"(lo), "f"(hi)); return r;
}
__device__ __forceinline__ void upk2(u64 v, float& lo, float& hi) {
    asm("mov.b64 {%0,%1}, %2;" : "=f"(lo), "=f"(hi) : "l"(v));
}
__device__ __forceinline__ u64 ffma2(u64 a, u64 b, u64 c) {
    u64 d; asm("fma.rn.f32x2 %0, %1, %2, %3;" : "=l"(d) : "l"(a), "l"(b), "l"(c)); return d;
}

__global__ void zero_kernel(float* __restrict__ out, int n) {
    int i = blockIdx.x * blockDim.x + threadIdx.x;
    if (i < n) out[i] = 0.0f;
}

// h-PAIR packed scheme. For h2 in [0,32): lanes of each packed reg hold
// (h=2*h2, h=2*h2+1). Weight block per h2: 16 u64 (128 bytes):
//   s in [0,DIN)      : (W1[s,2h2], W1[s,2h2+1])
//   s == DIN          : (b1[2h2],  b1[2h2+1])
//   s in (DIN,DIN+9]  : (W2[2h2,m], W2[2h2+1,m]),  m = s-DIN-1
// Accumulators stay packed (even-h sum in lane0, odd-h in lane1); merged with
// one FADD per output in the epilogue. b2 seeded into lane0 only.
template<int DIN, int EPT>
__device__ __forceinline__ void run_family(
    const float* __restrict__ x,
    const int*   __restrict__ edges,
    const float* __restrict__ attr,
    const float* __restrict__ W1, const float* __restrict__ b1,
    const float* __restrict__ W2, const float* __restrict__ b2,
    float* __restrict__ out, int E, int blk, int nblk, u64* smem)
{
    u64* sWB = smem;             // [16 * 32]
    u64* sB2 = sWB + 16 * 32;    // [9], (b2, 0)

    for (int idx = threadIdx.x; idx < 16 * 32; idx += blockDim.x) {
        int h2 = idx >> 4, s = idx & 15;
        int h0 = 2 * h2, h1 = 2 * h2 + 1;
        float lo = 0.0f, hi = 0.0f;
        if (s < DIN)           { lo = W1[s * HID + h0]; hi = W1[s * HID + h1]; }
        else if (s == DIN)     { lo = b1[h0];           hi = b1[h1]; }
        else if (s <= DIN + 9) { int m = s - DIN - 1; lo = W2[h0 * 9 + m]; hi = W2[h1 * 9 + m]; }
        sWB[idx] = pk2(lo, hi);
    }
    if (threadIdx.x < 9) sB2[threadIdx.x] = pk2(b2[threadIdx.x], 0.0f);
    __syncthreads();

    const int famTid     = blk * (int)blockDim.x + (int)threadIdx.x;
    const int famThreads = nblk * (int)blockDim.x;

    u64  dd[EPT][DIN];     // (d,d) duplicated MLP inputs
    u64  acc[EPT][9];      // packed accumulators (even-h, odd-h)
    int  tgt[EPT];
    bool valid[EPT];

    #pragma unroll
    for (int k = 0; k < EPT; k++) {
        int e = famTid + k * famThreads;
        valid[k] = (e < E);
        int ee = valid[k] ? e : 0;
        float dv[DIN];
        int i;
        if (DIN == 3) {
            int j = edges[ee];
            i = edges[E + ee];
            dv[0] = x[3*j+0] - x[3*i+0];
            dv[1] = x[3*j+1] - x[3*i+1];
            dv[2] = x[3*j+2] - x[3*i+2];
        } else {
            int j  = edges[ee];
            int kk = edges[E + ee];
            i = edges[2*E + ee];
            float xk0 = x[3*kk+0], xk1 = x[3*kk+1], xk2 = x[3*kk+2];
            dv[0] = xk0 - x[3*j+0];
            dv[1] = xk1 - x[3*j+1];
            dv[2] = xk2 - x[3*j+2];
            dv[3] = x[3*i+0] - xk0;
            dv[4] = x[3*i+1] - xk1;
            dv[5] = x[3*i+2] - xk2;
        }
        tgt[k] = i;
        #pragma unroll
        for (int q = 0; q < DIN; q++) dd[k][q] = pk2(dv[q], dv[q]);
        #pragma unroll
        for (int m = 0; m < 9; m++) acc[k][m] = sB2[m];
    }

    // Mainloop: 32 iterations over h-pairs. Weights via LDS.128, indexed
    // directly from a small vector array (no renamed copies).
    #pragma unroll 2
    for (int h2 = 0; h2 < 32; h2++) {
        const ulonglong2* wrow = (const ulonglong2*)(sWB + h2 * 16);
        constexpr int NQ = (DIN + 1 + 9 + 1) / 2;   // 7 for DIN=3, 8 for DIN=6
        ulonglong2 qv[NQ];
        #pragma unroll
        for (int i = 0; i < NQ; i++) qv[i] = wrow[i];

        #pragma unroll
        for (int k = 0; k < EPT; k++) {
            u64 hv = (DIN & 1) ? qv[DIN >> 1].y : qv[DIN >> 1].x;   // b1 pair
            #pragma unroll
            for (int i = 0; i < DIN; i++)
                hv = ffma2(dd[k][i], (i & 1) ? qv[i >> 1].y : qv[i >> 1].x, hv);
            float lo, hi; upk2(hv, lo, hi);
            lo = fmaxf(lo, 0.0f); hi = fmaxf(hi, 0.0f);
            hv = pk2(lo, hi);
            #pragma unroll
            for (int m = 0; m < 9; m++) {
                int s = DIN + 1 + m;
                acc[k][m] = ffma2(hv, (s & 1) ? qv[s >> 1].y : qv[s >> 1].x, acc[k][m]);
            }
        }
    }

    // Epilogue: merge h-lanes, matvec with attr, scatter-add.
    #pragma unroll
    for (int k = 0; k < EPT; k++) {
        if (!valid[k]) continue;
        int e = famTid + k * famThreads;
        float a0 = attr[3*e+0], a1 = attr[3*e+1], a2v = attr[3*e+2];
        #pragma unroll
        for (int i = 0; i < 3; i++) {
            float m0lo, m0hi, m1lo, m1hi, m2lo, m2hi;
            upk2(acc[k][3*i+0], m0lo, m0hi);
            upk2(acc[k][3*i+1], m1lo, m1hi);
            upk2(acc[k][3*i+2], m2lo, m2hi);
            float y = fmaf(m0lo + m0hi, a0,
                      fmaf(m1lo + m1hi, a1,
                           (m2lo + m2hi) * a2v));
            atomicAdd(&out[3*tgt[k] + i], y);
        }
    }
}

__global__ __launch_bounds__(128)
void fused_hignn_kernel(
    const float* __restrict__ x,
    const int* __restrict__ e2, const float* __restrict__ a2,
    const float* __restrict__ W1_2b, const float* __restrict__ b1_2b,
    const float* __restrict__ W2_2b, const float* __restrict__ b2_2b,
    const int* __restrict__ e3, const float* __restrict__ a3,
    const float* __restrict__ W1_3b, const float* __restrict__ b1_3b,
    const float* __restrict__ W2_3b, const float* __restrict__ b2_3b,
    const int* __restrict__ es, const float* __restrict__ as,
    const float* __restrict__ W1_s, const float* __restrict__ b1_s,
    const float* __restrict__ W2_s, const float* __restrict__ b2_s,
    float* __restrict__ out,
    int E2, int E3, int ES, int B2, int B3, int BS)
{
    __shared__ __align__(16) u64 smem[16 * 32 + 9];
    int b = blockIdx.x;
    if (b < B2) {
        run_family<3, 2>(x, e2, a2, W1_2b, b1_2b, W2_2b, b2_2b, out, E2, b, B2, smem);
    } else if (b < B2 + B3) {
        run_family<6, 2>(x, e3, a3, W1_3b, b1_3b, W2_3b, b2_3b, out, E3, b - B2, B3, smem);
    } else {
        run_family<3, 2>(x, es, as, W1_s, b1_s, W2_s, b2_s, out, ES, b - B2 - B3, BS, smem);
    }
}

extern "C" void kernel_launch(void* const* d_in, const int* in_sizes, int n_in,
                              void* d_out, int out_size)
{
    const float* x   = (const float*)d_in[0];
    const int*   e2  = (const int*)  d_in[1];
    const int*   e3  = (const int*)  d_in[2];
    const int*   es  = (const int*)  d_in[3];
    const float* a2  = (const float*)d_in[5];
    const float* a3  = (const float*)d_in[6];
    const float* as  = (const float*)d_in[7];
    const float* W1_2b = (const float*)d_in[9];
    const float* b1_2b = (const float*)d_in[10];
    const float* W2_2b = (const float*)d_in[11];
    const float* b2_2b = (const float*)d_in[12];
    const float* W1_3b = (const float*)d_in[13];
    const float* b1_3b = (const float*)d_in[14];
    const float* W2_3b = (const float*)d_in[15];
    const float* b2_3b = (const float*)d_in[16];
    const float* W1_s  = (const float*)d_in[17];
    const float* b1_s  = (const float*)d_in[18];
    const float* W2_s  = (const float*)d_in[19];
    const float* b2_s  = (const float*)d_in[20];

    const int E2 = in_sizes[1] / 2;
    const int E3 = in_sizes[2] / 3;
    const int ES = in_sizes[3] / 2;

    float* out = (float*)d_out;

    zero_kernel<<<(out_size + 255) / 256, 256>>>(out, out_size);

    constexpr int EPT = 2;
    constexpr int BLK = 128;
    const int B2 = (E2 + EPT * BLK - 1) / (EPT * BLK);
    const int B3 = (E3 + EPT * BLK - 1) / (EPT * BLK);
    const int BS = (ES + EPT * BLK - 1) / (EPT * BLK);

    fused_hignn_kernel<<<B2 + B3 + BS, BLK>>>(
        x,
        e2, a2, W1_2b, b1_2b, W2_2b, b2_2b,
        e3, a3, W1_3b, b1_3b, W2_3b, b2_3b,
        es, as, W1_s, b1_s, W2_s, b2_s,
        out, E2, E3, ES, B2, B3, BS);
}

// round 5
// speedup vs baseline: 1.1189x; 1.0255x over previous
#include <cuda_runtime.h>

#define HID 64
typedef unsigned long long u64;

__device__ __forceinline__ u64 pk2(float lo, float hi) {
    u64 r; asm("mov.b64 %0, {%1,%2};" : "=l"(r) : "f"(lo), "f"(hi)); return r;
}
__device__ __forceinline__ void upk2(u64 v, float& lo, float& hi) {
    asm("mov.b64 {%0,%1}, %2;" : "=f"(lo), "=f"(hi) : "l"(v));
}
__device__ __forceinline__ u64 ffma2(u64 a, u64 b, u64 c) {
    u64 d; asm("fma.rn.f32x2 %0, %1, %2, %3;" : "=l"(d) : "l"(a), "l"(b), "l"(c)); return d;
}

__global__ void zero_kernel(float* __restrict__ out, int n) {
    int i = blockIdx.x * blockDim.x + threadIdx.x;
    if (i < n) out[i] = 0.0f;
}

// h-PAIR packed scheme + edge register blocking.
// For h2 in [0,32): packed regs hold (h=2*h2, h=2*h2+1). Weight block per h2:
// 16 u64 (128B):
//   s in [0,DIN)      : (W1[s,2h2], W1[s,2h2+1])
//   s == DIN          : (b1[2h2],  b1[2h2+1])
//   s in (DIN,DIN+9]  : (W2[2h2,m], W2[2h2+1,m]),  m = s-DIN-1
// Accumulators packed (even-h sum lane0, odd-h lane1), merged in epilogue.
// EPT edges per thread amortize the per-h2 weight LDS over more FFMA2.
template<int DIN, int EPT>
__device__ __forceinline__ void run_family(
    const float* __restrict__ x,
    const int*   __restrict__ edges,
    const float* __restrict__ attr,
    const float* __restrict__ W1, const float* __restrict__ b1,
    const float* __restrict__ W2, const float* __restrict__ b2,
    float* __restrict__ out, int E, int blk, int nblk, u64* smem)
{
    u64* sWB = smem;             // [16 * 32]
    u64* sB2 = sWB + 16 * 32;    // [9], (b2, 0)

    for (int idx = threadIdx.x; idx < 16 * 32; idx += blockDim.x) {
        int h2 = idx >> 4, s = idx & 15;
        int h0 = 2 * h2, h1 = 2 * h2 + 1;
        float lo = 0.0f, hi = 0.0f;
        if (s < DIN)           { lo = W1[s * HID + h0]; hi = W1[s * HID + h1]; }
        else if (s == DIN)     { lo = b1[h0];           hi = b1[h1]; }
        else if (s <= DIN + 9) { int m = s - DIN - 1; lo = W2[h0 * 9 + m]; hi = W2[h1 * 9 + m]; }
        sWB[idx] = pk2(lo, hi);
    }
    if (threadIdx.x < 9) sB2[threadIdx.x] = pk2(b2[threadIdx.x], 0.0f);
    __syncthreads();

    const int famTid     = blk * (int)blockDim.x + (int)threadIdx.x;
    const int famThreads = nblk * (int)blockDim.x;

    u64  dd[EPT][DIN];     // (d,d) duplicated MLP inputs
    u64  acc[EPT][9];      // packed accumulators (even-h, odd-h)
    int  tgt[EPT];
    bool valid[EPT];

    #pragma unroll
    for (int k = 0; k < EPT; k++) {
        int e = famTid + k * famThreads;
        valid[k] = (e < E);
        int ee = valid[k] ? e : 0;
        float dv[DIN];
        int i;
        if (DIN == 3) {
            int j = edges[ee];
            i = edges[E + ee];
            dv[0] = x[3*j+0] - x[3*i+0];
            dv[1] = x[3*j+1] - x[3*i+1];
            dv[2] = x[3*j+2] - x[3*i+2];
        } else {
            int j  = edges[ee];
            int kk = edges[E + ee];
            i = edges[2*E + ee];
            float xk0 = x[3*kk+0], xk1 = x[3*kk+1], xk2 = x[3*kk+2];
            dv[0] = xk0 - x[3*j+0];
            dv[1] = xk1 - x[3*j+1];
            dv[2] = xk2 - x[3*j+2];
            dv[3] = x[3*i+0] - xk0;
            dv[4] = x[3*i+1] - xk1;
            dv[5] = x[3*i+2] - xk2;
        }
        tgt[k] = i;
        #pragma unroll
        for (int q = 0; q < DIN; q++) dd[k][q] = pk2(dv[q], dv[q]);
        #pragma unroll
        for (int m = 0; m < 9; m++) acc[k][m] = sB2[m];
    }

    // Mainloop: 32 h-pair iterations. Per iter: NQ LDS.128 feed EPT*(DIN+1+9)
    // packed FMAs. Direct .x/.y indexing — no staging copies.
    #pragma unroll 2
    for (int h2 = 0; h2 < 32; h2++) {
        const ulonglong2* wrow = (const ulonglong2*)(sWB + h2 * 16);
        constexpr int NQ = (DIN + 1 + 9 + 1) / 2;   // 7 (DIN=3), 8 (DIN=6)
        ulonglong2 qv[NQ];
        #pragma unroll
        for (int i = 0; i < NQ; i++) qv[i] = wrow[i];

        #pragma unroll
        for (int k = 0; k < EPT; k++) {
            u64 hv = (DIN & 1) ? qv[DIN >> 1].y : qv[DIN >> 1].x;   // b1 pair
            #pragma unroll
            for (int i = 0; i < DIN; i++)
                hv = ffma2(dd[k][i], (i & 1) ? qv[i >> 1].y : qv[i >> 1].x, hv);
            float lo, hi; upk2(hv, lo, hi);
            lo = fmaxf(lo, 0.0f); hi = fmaxf(hi, 0.0f);
            hv = pk2(lo, hi);
            #pragma unroll
            for (int m = 0; m < 9; m++) {
                int s = DIN + 1 + m;
                acc[k][m] = ffma2(hv, (s & 1) ? qv[s >> 1].y : qv[s >> 1].x, acc[k][m]);
            }
        }
    }

    // Epilogue: merge h-lanes, matvec with attr, scatter-add.
    #pragma unroll
    for (int k = 0; k < EPT; k++) {
        if (!valid[k]) continue;
        int e = famTid + k * famThreads;
        float a0 = attr[3*e+0], a1 = attr[3*e+1], a2v = attr[3*e+2];
        #pragma unroll
        for (int i = 0; i < 3; i++) {
            float m0lo, m0hi, m1lo, m1hi, m2lo, m2hi;
            upk2(acc[k][3*i+0], m0lo, m0hi);
            upk2(acc[k][3*i+1], m1lo, m1hi);
            upk2(acc[k][3*i+2], m2lo, m2hi);
            float y = fmaf(m0lo + m0hi, a0,
                      fmaf(m1lo + m1hi, a1,
                           (m2lo + m2hi) * a2v));
            atomicAdd(&out[3*tgt[k] + i], y);
        }
    }
}

#define EPT3B 4   // edges/thread for DIN=3 families
#define EPT6B 3   // edges/thread for DIN=6 family (register budget)

__global__ __launch_bounds__(128)
void fused_hignn_kernel(
    const float* __restrict__ x,
    const int* __restrict__ e2, const float* __restrict__ a2,
    const float* __restrict__ W1_2b, const float* __restrict__ b1_2b,
    const float* __restrict__ W2_2b, const float* __restrict__ b2_2b,
    const int* __restrict__ e3, const float* __restrict__ a3,
    const float* __restrict__ W1_3b, const float* __restrict__ b1_3b,
    const float* __restrict__ W2_3b, const float* __restrict__ b2_3b,
    const int* __restrict__ es, const float* __restrict__ as,
    const float* __restrict__ W1_s, const float* __restrict__ b1_s,
    const float* __restrict__ W2_s, const float* __restrict__ b2_s,
    float* __restrict__ out,
    int E2, int E3, int ES, int B2, int B3, int BS)
{
    __shared__ __align__(16) u64 smem[16 * 32 + 9];
    int b = blockIdx.x;
    if (b < B2) {
        run_family<3, EPT3B>(x, e2, a2, W1_2b, b1_2b, W2_2b, b2_2b, out, E2, b, B2, smem);
    } else if (b < B2 + B3) {
        run_family<6, EPT6B>(x, e3, a3, W1_3b, b1_3b, W2_3b, b2_3b, out, E3, b - B2, B3, smem);
    } else {
        run_family<3, EPT3B>(x, es, as, W1_s, b1_s, W2_s, b2_s, out, ES, b - B2 - B3, BS, smem);
    }
}

extern "C" void kernel_launch(void* const* d_in, const int* in_sizes, int n_in,
                              void* d_out, int out_size)
{
    const float* x   = (const float*)d_in[0];
    const int*   e2  = (const int*)  d_in[1];
    const int*   e3  = (const int*)  d_in[2];
    const int*   es  = (const int*)  d_in[3];
    const float* a2  = (const float*)d_in[5];
    const float* a3  = (const float*)d_in[6];
    const float* as  = (const float*)d_in[7];
    const float* W1_2b = (const float*)d_in[9];
    const float* b1_2b = (const float*)d_in[10];
    const float* W2_2b = (const float*)d_in[11];
    const float* b2_2b = (const float*)d_in[12];
    const float* W1_3b = (const float*)d_in[13];
    const float* b1_3b = (const float*)d_in[14];
    const float* W2_3b = (const float*)d_in[15];
    const float* b2_3b = (const float*)d_in[16];
    const float* W1_s  = (const float*)d_in[17];
    const float* b1_s  = (const float*)d_in[18];
    const float* W2_s  = (const float*)d_in[19];
    const float* b2_s  = (const float*)d_in[20];

    const int E2 = in_sizes[1] / 2;
    const int E3 = in_sizes[2] / 3;
    const int ES = in_sizes[3] / 2;

    float* out = (float*)d_out;

    zero_kernel<<<(out_size + 255) / 256, 256>>>(out, out_size);

    constexpr int BLK = 128;
    const int B2 = (E2 + EPT3B * BLK - 1) / (EPT3B * BLK);
    const int B3 = (E3 + EPT6B * BLK - 1) / (EPT6B * BLK);
    const int BS = (ES + EPT3B * BLK - 1) / (EPT3B * BLK);

    fused_hignn_kernel<<<B2 + B3 + BS, BLK>>>(
        x,
        e2, a2, W1_2b, b1_2b, W2_2b, b2_2b,
        e3, a3, W1_3b, b1_3b, W2_3b, b2_3b,
        es, as, W1_s, b1_s, W2_s, b2_s,
        out, E2, E3, ES, B2, B3, BS);
}